// round 2
// baseline (speedup 1.0000x reference)
#include <cuda_runtime.h>

// CosineSim3D: out[b,n,d] = softmax_n( (a_n · s_b) / |a_n| ) tiled over d
// where s_b = sum_m b_m / |b_m| , norms clamped at sqrt(max(ss, 1e-7)).
//
// a, b : [128, 1024, 300] fp32   out : [128, 1024, 300] fp32

#define BATCH   128
#define NROWS   1024
#define DIM     300
#define NCHUNK  10          // ceil(300/32)
#define EPSV    1e-7f

// scratch: per-batch summed normalized-b vector (no cudaMalloc allowed)
__device__ float g_s[BATCH * DIM];

// ---------------------------------------------------------------------------
// Kernel A: s[b][:] = sum over 1024 rows of b_row / max(|b_row|, sqrt(eps))
// grid = 128 (batch), block = 1024 (32 warps, warp-per-row strided)
// ---------------------------------------------------------------------------
__global__ __launch_bounds__(1024) void sumnorm_kernel(const float* __restrict__ b)
{
    const int batch = blockIdx.x;
    const int warp  = threadIdx.x >> 5;
    const int lane  = threadIdx.x & 31;

    const float* bb = b + (size_t)batch * NROWS * DIM;

    float acc[NCHUNK];
#pragma unroll
    for (int k = 0; k < NCHUNK; k++) acc[k] = 0.f;

    for (int r = warp; r < NROWS; r += 32) {
        const float* row = bb + r * DIM;
        float v[NCHUNK];
        float ss = 0.f;
#pragma unroll
        for (int k = 0; k < NCHUNK; k++) {
            const int j = k * 32 + lane;
            v[k] = (j < DIM) ? __ldg(row + j) : 0.f;
            ss += v[k] * v[k];
        }
#pragma unroll
        for (int o = 16; o > 0; o >>= 1)
            ss += __shfl_xor_sync(0xffffffffu, ss, o);
        const float inv = rsqrtf(fmaxf(ss, EPSV));
#pragma unroll
        for (int k = 0; k < NCHUNK; k++) acc[k] += v[k] * inv;
    }

    // cross-warp reduce: 32 warps x 300 dims through shared
    __shared__ float sw[32][DIM + 4];   // +4 pad to decorrelate banks
#pragma unroll
    for (int k = 0; k < NCHUNK; k++) {
        const int j = k * 32 + lane;
        if (j < DIM) sw[warp][j] = acc[k];
    }
    __syncthreads();

    for (int j = threadIdx.x; j < DIM; j += blockDim.x) {
        float t = 0.f;
#pragma unroll
        for (int w = 0; w < 32; w++) t += sw[w][j];
        g_s[batch * DIM + j] = t;
    }
}

// ---------------------------------------------------------------------------
// Kernel B: scores -> softmax -> tiled float4 broadcast write
// grid = 128 (batch), block = 1024
// ---------------------------------------------------------------------------
__global__ __launch_bounds__(1024) void score_softmax_write_kernel(
    const float* __restrict__ a, float* __restrict__ out)
{
    const int batch = blockIdx.x;
    const int warp  = threadIdx.x >> 5;
    const int lane  = threadIdx.x & 31;

    __shared__ float ssh[DIM];
    __shared__ float probs[NROWS];
    __shared__ float red[32];

    for (int j = threadIdx.x; j < DIM; j += blockDim.x)
        ssh[j] = g_s[batch * DIM + j];
    __syncthreads();

    const float* ab = a + (size_t)batch * NROWS * DIM;

    // scores: warp-per-row
    for (int r = warp; r < NROWS; r += 32) {
        const float* row = ab + r * DIM;
        float dot = 0.f, ss = 0.f;
#pragma unroll
        for (int k = 0; k < NCHUNK; k++) {
            const int j = k * 32 + lane;
            const bool ok = (j < DIM);
            const float v  = ok ? __ldg(row + j) : 0.f;
            const float sv = ok ? ssh[j] : 0.f;
            dot += v * sv;
            ss  += v * v;
        }
#pragma unroll
        for (int o = 16; o > 0; o >>= 1) {
            dot += __shfl_xor_sync(0xffffffffu, dot, o);
            ss  += __shfl_xor_sync(0xffffffffu, ss,  o);
        }
        if (lane == 0)
            probs[r] = dot * rsqrtf(fmaxf(ss, EPSV));
    }
    __syncthreads();

    // block softmax over 1024 scores (thread t owns element t)
    const float x = probs[threadIdx.x];

    // block max
    float m = x;
#pragma unroll
    for (int o = 16; o > 0; o >>= 1)
        m = fmaxf(m, __shfl_xor_sync(0xffffffffu, m, o));
    if (lane == 0) red[warp] = m;
    __syncthreads();
    if (warp == 0) {
        float t = red[lane];
#pragma unroll
        for (int o = 16; o > 0; o >>= 1)
            t = fmaxf(t, __shfl_xor_sync(0xffffffffu, t, o));
        if (lane == 0) red[0] = t;
    }
    __syncthreads();
    const float M = red[0];

    const float e = __expf(x - M);

    // block sum
    float sum = e;
#pragma unroll
    for (int o = 16; o > 0; o >>= 1)
        sum += __shfl_xor_sync(0xffffffffu, sum, o);
    __syncthreads();           // red[] reuse: wait until max phase fully read
    if (lane == 0) red[warp] = sum;
    __syncthreads();
    if (warp == 0) {
        float t = red[lane];
#pragma unroll
        for (int o = 16; o > 0; o >>= 1)
            t += __shfl_xor_sync(0xffffffffu, t, o);
        if (lane == 0) red[0] = t;
    }
    __syncthreads();
    const float invE = __frcp_rn(red[0]);

    probs[threadIdx.x] = e * invE;
    __syncthreads();

    // broadcast write: 1024 rows x 300 floats = 1024 x 75 float4
    float4* o4 = reinterpret_cast<float4*>(out + (size_t)batch * NROWS * DIM);
    const int total4 = NROWS * (DIM / 4);   // 76800
    for (int i = threadIdx.x; i < total4; i += blockDim.x) {
        const int r = i / (DIM / 4);
        const float p = probs[r];
        o4[i] = make_float4(p, p, p, p);
    }
}

// ---------------------------------------------------------------------------
extern "C" void kernel_launch(void* const* d_in, const int* in_sizes, int n_in,
                              void* d_out, int out_size)
{
    const float* a = (const float*)d_in[0];
    const float* b = (const float*)d_in[1];
    float* out = (float*)d_out;

    sumnorm_kernel<<<BATCH, 1024>>>(b);
    score_softmax_write_kernel<<<BATCH, 1024>>>(a, out);
}

// round 3
// speedup vs baseline: 1.0101x; 1.0101x over previous
#include <cuda_runtime.h>

// CosineSim3D factorized:
//   s_b       = sum_m b_m / max(|b_m|, sqrt(eps))
//   score[n]  = (a_n · s_b) / max(|a_n|, sqrt(eps))
//   probs     = softmax_n(score)
//   out[b,n,:]= probs[b,n]  (broadcast over 300)
//
// a, b : [128, 1024, 300] fp32   out : [128, 1024, 300] fp32

#define BATCH   128
#define NROWS   1024
#define DIM     300
#define NF4     75          // 300 / 4
#define EPSV    1e-7f

// scratch (no cudaMalloc allowed): per-(batch,row) softmax probs
__device__ float g_probs[BATCH * NROWS];

__device__ __forceinline__ float dot4(float4 x, float4 y) {
    return x.x * y.x + x.y * y.y + x.z * y.z + x.w * y.w;
}

// ---------------------------------------------------------------------------
// Kernel 1 (fused): per batch — sum normalized b rows, score a rows against
// it, softmax, write probs. Pure-read streaming of 314 MB + 512 KB write.
// grid = 128 (batch), block = 1024 (32 warps, warp-per-row)
// ---------------------------------------------------------------------------
__global__ __launch_bounds__(1024) void fused_score_kernel(
    const float* __restrict__ a, const float* __restrict__ b)
{
    const int batch = blockIdx.x;
    const int warp  = threadIdx.x >> 5;
    const int lane  = threadIdx.x & 31;

    __shared__ float4 sw4[32][NF4 + 1];   // cross-warp partials (+1 pad)
    __shared__ float4 ssh4[NF4];          // s_b vector
    __shared__ float  probs[NROWS];
    __shared__ float  red[32];

    const float4 zero4 = make_float4(0.f, 0.f, 0.f, 0.f);

    // ---- phase 1: s_b = sum of normalized b rows -------------------------
    {
        const float4* b4 = reinterpret_cast<const float4*>(
            b + (size_t)batch * NROWS * DIM);
        float4 acc0 = zero4, acc1 = zero4, acc2 = zero4;

        for (int r = warp; r < NROWS; r += 32) {
            const float4* row = b4 + r * NF4;
            const float4 v0 = __ldg(row + lane);
            const float4 v1 = __ldg(row + lane + 32);
            const float4 v2 = (lane < NF4 - 64) ? __ldg(row + lane + 64) : zero4;
            float ss = dot4(v0, v0) + dot4(v1, v1) + dot4(v2, v2);
#pragma unroll
            for (int o = 16; o > 0; o >>= 1)
                ss += __shfl_xor_sync(0xffffffffu, ss, o);
            const float inv = rsqrtf(fmaxf(ss, EPSV));
            acc0.x += v0.x * inv; acc0.y += v0.y * inv;
            acc0.z += v0.z * inv; acc0.w += v0.w * inv;
            acc1.x += v1.x * inv; acc1.y += v1.y * inv;
            acc1.z += v1.z * inv; acc1.w += v1.w * inv;
            acc2.x += v2.x * inv; acc2.y += v2.y * inv;
            acc2.z += v2.z * inv; acc2.w += v2.w * inv;
        }
        sw4[warp][lane]      = acc0;
        sw4[warp][lane + 32] = acc1;
        if (lane < NF4 - 64) sw4[warp][lane + 64] = acc2;
    }
    __syncthreads();

    // reduce 32 warp-partials -> ssh4
    for (int j = threadIdx.x; j < NF4; j += blockDim.x) {
        float4 t = zero4;
#pragma unroll
        for (int w = 0; w < 32; w++) {
            const float4 p = sw4[w][j];
            t.x += p.x; t.y += p.y; t.z += p.z; t.w += p.w;
        }
        ssh4[j] = t;
    }
    __syncthreads();

    // ---- phase 2: scores of a rows ---------------------------------------
    {
        const float4* a4 = reinterpret_cast<const float4*>(
            a + (size_t)batch * NROWS * DIM);
        const float4 s0 = ssh4[lane];
        const float4 s1 = ssh4[lane + 32];
        const float4 s2 = (lane < NF4 - 64) ? ssh4[lane + 64] : zero4;

        for (int r = warp; r < NROWS; r += 32) {
            const float4* row = a4 + r * NF4;
            const float4 v0 = __ldg(row + lane);
            const float4 v1 = __ldg(row + lane + 32);
            const float4 v2 = (lane < NF4 - 64) ? __ldg(row + lane + 64) : zero4;
            float dot = dot4(v0, s0) + dot4(v1, s1) + dot4(v2, s2);
            float ss  = dot4(v0, v0) + dot4(v1, v1) + dot4(v2, v2);
#pragma unroll
            for (int o = 16; o > 0; o >>= 1) {
                dot += __shfl_xor_sync(0xffffffffu, dot, o);
                ss  += __shfl_xor_sync(0xffffffffu, ss,  o);
            }
            if (lane == 0)
                probs[r] = dot * rsqrtf(fmaxf(ss, EPSV));
        }
    }
    __syncthreads();

    // ---- phase 3: softmax over 1024 scores (thread t owns element t) -----
    const float x = probs[threadIdx.x];

    float m = x;
#pragma unroll
    for (int o = 16; o > 0; o >>= 1)
        m = fmaxf(m, __shfl_xor_sync(0xffffffffu, m, o));
    if (lane == 0) red[warp] = m;
    __syncthreads();
    if (warp == 0) {
        float t = red[lane];
#pragma unroll
        for (int o = 16; o > 0; o >>= 1)
            t = fmaxf(t, __shfl_xor_sync(0xffffffffu, t, o));
        if (lane == 0) red[0] = t;
    }
    __syncthreads();
    const float M = red[0];

    const float e = __expf(x - M);

    float sum = e;
#pragma unroll
    for (int o = 16; o > 0; o >>= 1)
        sum += __shfl_xor_sync(0xffffffffu, sum, o);
    __syncthreads();                 // red[] reuse barrier
    if (lane == 0) red[warp] = sum;
    __syncthreads();
    if (warp == 0) {
        float t = red[lane];
#pragma unroll
        for (int o = 16; o > 0; o >>= 1)
            t += __shfl_xor_sync(0xffffffffu, t, o);
        if (lane == 0) red[0] = t;
    }
    __syncthreads();

    g_probs[batch * NROWS + threadIdx.x] = e * __frcp_rn(red[0]);
}

// ---------------------------------------------------------------------------
// Kernel 2: pure-write broadcast. probs (512 KB) is L2-resident; out is a
// fully coalesced float4 stream. Full-grid for max write BW.
// ---------------------------------------------------------------------------
__global__ __launch_bounds__(512) void broadcast_write_kernel(
    float* __restrict__ out)
{
    const int total4 = BATCH * NROWS * NF4;        // 9,830,400
    float4* o4 = reinterpret_cast<float4*>(out);
    const int stride = gridDim.x * blockDim.x;

    for (int i = blockIdx.x * blockDim.x + threadIdx.x; i < total4; i += stride) {
        const int r = i / NF4;                      // (batch*NROWS + row)
        const float p = __ldg(g_probs + r);
        o4[i] = make_float4(p, p, p, p);
    }
}

// ---------------------------------------------------------------------------
extern "C" void kernel_launch(void* const* d_in, const int* in_sizes, int n_in,
                              void* d_out, int out_size)
{
    const float* a = (const float*)d_in[0];
    const float* b = (const float*)d_in[1];
    float* out = (float*)d_out;

    fused_score_kernel<<<BATCH, 1024>>>(a, b);
    broadcast_write_kernel<<<1184, 512>>>(out);   // 148 SMs x 8 blocks
}